// round 2
// baseline (speedup 1.0000x reference)
#include <cuda_runtime.h>

// BoxQueryAndGroup: B=4, N=16384, C=64, NQ=256, S=32
//
// Reference semantics: idx_f = in_box * arange(N); argsort ascending STABLE,
// take first 32. Zero-keys = {n : !in_box[n]} ∪ {0}. With >=84% of points
// out-of-box, the result is the 32 smallest indices with (n==0 || !in_box),
// ascending. Fallback (never expected to trigger): if fewer than 32 zero-keys,
// the sort continues with in-box indices (key = n) ascending.
// local_group_mask: idx_sorted[0]==0 always (forced False at s=0); s>0 indices
// are distinct nonzero => mask is identically False => write 0.0f.
//
// Outputs concatenated flat, float32:
//   grouped_xyz  (B,3,NQ,S)   = 98304
//   new_features (B,67,NQ,S)  = 2195456
//   mask         (B,NQ,S)     = 32768
//   total                     = 2326528

#define BQ_B  4
#define BQ_N  16384
#define BQ_C  64
#define BQ_NQ 256
#define BQ_S  32

#define WARPS_PER_BLOCK 4

__global__ __launch_bounds__(WARPS_PER_BLOCK * 32)
void boxquery_group_kernel(const float* __restrict__ key_xyz,     // (B,N,3)
                           const float* __restrict__ key_feat,    // (B,C,N)
                           const float* __restrict__ query_box,   // (B,NQ,6)
                           float* __restrict__ out) {
    const int warpId = threadIdx.x >> 5;
    const int lane   = threadIdx.x & 31;
    const int w      = blockIdx.x * WARPS_PER_BLOCK + warpId;
    if (w >= BQ_B * BQ_NQ) return;
    const int b = w / BQ_NQ;
    const int q = w % BQ_NQ;

    __shared__ int s_sel[WARPS_PER_BLOCK][BQ_S];

    const float* qb = query_box + ((size_t)b * BQ_NQ + q) * 6;
    const float cx = qb[0], cy = qb[1], cz = qb[2];
    const float hx = 0.5f * qb[3], hy = 0.5f * qb[4], hz = 0.5f * qb[5];

    const float* xyzb = key_xyz + (size_t)b * BQ_N * 3;

    s_sel[warpId][lane] = 0;
    __syncwarp();

    // Pass 1: zero-key indices (n==0 or not-in-box), ascending.
    int count = 0;
    int base  = 0;
    while (count < BQ_S && base < BQ_N) {
        const int n = base + lane;
        bool cand = false;
        if (n < BQ_N) {
            const float x = xyzb[n * 3 + 0];
            const float y = xyzb[n * 3 + 1];
            const float z = xyzb[n * 3 + 2];
            const bool inb = (fabsf(x - cx) <= hx) &&
                             (fabsf(y - cy) <= hy) &&
                             (fabsf(z - cz) <= hz);
            cand = (n == 0) || !inb;
        }
        const unsigned m = __ballot_sync(0xffffffffu, cand);
        const int slot = count + __popc(m & ((1u << lane) - 1u));
        if (cand && slot < BQ_S) s_sel[warpId][slot] = n;
        count += __popc(m);
        base  += 32;
    }

    // Pass 2 (theoretical fallback): in-box indices with n>0, key=n ascending.
    if (count < BQ_S) {
        base = 0;
        while (count < BQ_S && base < BQ_N) {
            const int n = base + lane;
            bool cand = false;
            if (n < BQ_N && n != 0) {
                const float x = xyzb[n * 3 + 0];
                const float y = xyzb[n * 3 + 1];
                const float z = xyzb[n * 3 + 2];
                cand = (fabsf(x - cx) <= hx) &&
                       (fabsf(y - cy) <= hy) &&
                       (fabsf(z - cz) <= hz);
            }
            const unsigned m = __ballot_sync(0xffffffffu, cand);
            const int slot = count + __popc(m & ((1u << lane) - 1u));
            if (cand && slot < BQ_S) s_sel[warpId][slot] = n;
            count += __popc(m);
            base  += 32;
        }
    }
    __syncwarp();

    const int idx = s_sel[warpId][lane];   // lane s holds idx_sorted[s]

    // Output section pointers
    float* gxyz = out;                                         // (B,3,NQ,S)
    float* nf   = out + (size_t)BQ_B * 3 * BQ_NQ * BQ_S;       // (B,67,NQ,S)
    float* mask = nf  + (size_t)BQ_B * (3 + BQ_C) * BQ_NQ * BQ_S; // (B,NQ,S)

    const float gx = xyzb[idx * 3 + 0] - cx;
    const float gy = xyzb[idx * 3 + 1] - cy;
    const float gz = xyzb[idx * 3 + 2] - cz;

    const size_t plane = (size_t)BQ_NQ * BQ_S;  // stride between channel planes
    const size_t gb = (size_t)b * 3 * plane + (size_t)q * BQ_S + lane;
    gxyz[gb]             = gx;
    gxyz[gb + plane]     = gy;
    gxyz[gb + 2 * plane] = gz;

    const size_t nb = (size_t)b * (3 + BQ_C) * plane + (size_t)q * BQ_S + lane;
    nf[nb]             = gx;
    nf[nb + plane]     = gy;
    nf[nb + 2 * plane] = gz;

    mask[(size_t)b * plane + (size_t)q * BQ_S + lane] = 0.0f;

    // Features: 64 channels gathered at idx, stores coalesced across lanes.
    const float* fb = key_feat + (size_t)b * BQ_C * BQ_N;
    const size_t ob = nb + 3 * plane;
    #pragma unroll 8
    for (int c = 0; c < BQ_C; c++) {
        nf[ob + (size_t)c * plane] = __ldg(&fb[(size_t)c * BQ_N + idx]);
    }
}

extern "C" void kernel_launch(void* const* d_in, const int* in_sizes, int n_in,
                              void* d_out, int out_size) {
    const float* key_xyz   = (const float*)d_in[0];
    const float* key_feat  = (const float*)d_in[1];
    const float* query_box = (const float*)d_in[2];
    float* out = (float*)d_out;

    const int total_warps = BQ_B * BQ_NQ;                    // 1024
    const int grid = (total_warps + WARPS_PER_BLOCK - 1) / WARPS_PER_BLOCK; // 256
    boxquery_group_kernel<<<grid, WARPS_PER_BLOCK * 32>>>(key_xyz, key_feat,
                                                          query_box, out);
}

// round 3
// speedup vs baseline: 1.0487x; 1.0487x over previous
#include <cuda_runtime.h>

// BoxQueryAndGroup: B=4, N=16384, C=64, NQ=256, S=32
//
// Reference semantics: idx_f = in_box * arange(N); stable argsort ascending,
// take first 32. Zero-keys = {n : !in_box[n]} ∪ {0}; since the vast majority
// of N(0,1) points fall outside boxes of half-size <= 0.75, the answer is the
// 32 smallest indices with (n==0 || !in_box), ascending. Fallback pass keeps
// exact argsort semantics if fewer than 32 zero-keys exist.
// local_group_mask is identically False (slot 0 forced False; slots>0 hold
// distinct nonzero indices) => write 0.0f.
//
// Outputs concatenated flat, float32:
//   grouped_xyz  (B,3,NQ,S)   = 98304
//   new_features (B,67,NQ,S)  = 2195456
//   mask         (B,NQ,S)     = 32768

#define BQ_B  4
#define BQ_N  16384
#define BQ_C  64
#define BQ_NQ 256
#define BQ_S  32

#define BQ_THREADS 256   // one block per (b,q); 8 warps

__global__ __launch_bounds__(BQ_THREADS)
void boxquery_group_kernel(const float* __restrict__ key_xyz,     // (B,N,3)
                           const float* __restrict__ key_feat,    // (B,C,N)
                           const float* __restrict__ query_box,   // (B,NQ,6)
                           float* __restrict__ out) {
    const int w = blockIdx.x;                 // (b,q) id, 0..1023
    const int b = w >> 8;                     // / BQ_NQ
    const int q = w & (BQ_NQ - 1);

    const int tid  = threadIdx.x;
    const int lane = tid & 31;
    const int wid  = tid >> 5;

    __shared__ int   s_idx[BQ_S];
    __shared__ float s_gx[BQ_S], s_gy[BQ_S], s_gz[BQ_S];

    const float* xyzb = key_xyz + (size_t)b * BQ_N * 3;

    // ---- Selection: warp 0 only ----
    if (wid == 0) {
        const float* qb = query_box + ((size_t)b * BQ_NQ + q) * 6;
        const float cx = qb[0], cy = qb[1], cz = qb[2];
        const float hx = 0.5f * qb[3], hy = 0.5f * qb[4], hz = 0.5f * qb[5];

        s_idx[lane] = 0;
        __syncwarp();

        // Pass 1: zero-key indices (n==0 or not-in-box), ascending.
        int count = 0;
        int base  = 0;
        while (count < BQ_S && base < BQ_N) {
            const int n = base + lane;
            bool cand = false;
            if (n < BQ_N) {
                const float x = xyzb[n * 3 + 0];
                const float y = xyzb[n * 3 + 1];
                const float z = xyzb[n * 3 + 2];
                const bool inb = (fabsf(x - cx) <= hx) &&
                                 (fabsf(y - cy) <= hy) &&
                                 (fabsf(z - cz) <= hz);
                cand = (n == 0) || !inb;
            }
            const unsigned m = __ballot_sync(0xffffffffu, cand);
            const int slot = count + __popc(m & ((1u << lane) - 1u));
            if (cand && slot < BQ_S) s_idx[slot] = n;
            count += __popc(m);
            base  += 32;
        }

        // Pass 2 (theoretical fallback): in-box indices n>0, key=n ascending.
        if (count < BQ_S) {
            base = 0;
            while (count < BQ_S && base < BQ_N) {
                const int n = base + lane;
                bool cand = false;
                if (n < BQ_N && n != 0) {
                    const float x = xyzb[n * 3 + 0];
                    const float y = xyzb[n * 3 + 1];
                    const float z = xyzb[n * 3 + 2];
                    cand = (fabsf(x - cx) <= hx) &&
                           (fabsf(y - cy) <= hy) &&
                           (fabsf(z - cz) <= hz);
                }
                const unsigned m = __ballot_sync(0xffffffffu, cand);
                const int slot = count + __popc(m & ((1u << lane) - 1u));
                if (cand && slot < BQ_S) s_idx[slot] = n;
                count += __popc(m);
                base  += 32;
            }
        }
        __syncwarp();

        const int idx = s_idx[lane];
        s_gx[lane] = xyzb[idx * 3 + 0] - cx;
        s_gy[lane] = xyzb[idx * 3 + 1] - cy;
        s_gz[lane] = xyzb[idx * 3 + 2] - cz;
    }
    __syncthreads();

    // ---- Writes: all 8 warps ----
    float* gxyz = out;                                              // (B,3,NQ,S)
    float* nf   = out + (size_t)BQ_B * 3 * BQ_NQ * BQ_S;            // (B,67,NQ,S)
    float* mask = nf  + (size_t)BQ_B * (3 + BQ_C) * BQ_NQ * BQ_S;   // (B,NQ,S)

    const size_t plane = (size_t)BQ_NQ * BQ_S;
    const size_t qs    = (size_t)q * BQ_S + lane;

    // xyz + mask handled by warps 0-3 (one row each), warp 3 does mask.
    if (wid < 3) {
        const float v = (wid == 0) ? s_gx[lane] : (wid == 1) ? s_gy[lane] : s_gz[lane];
        const size_t gb = ((size_t)b * 3 + wid) * plane + qs;
        gxyz[gb] = v;
        nf[((size_t)b * (3 + BQ_C) + wid) * plane + qs] = v;
    } else if (wid == 3) {
        mask[(size_t)b * plane + qs] = 0.0f;
    }

    // Features: warp wid handles channels c = wid*8 .. wid*8+7.
    const int idx = s_idx[lane];
    const float* fb = key_feat + (size_t)b * BQ_C * BQ_N;
    const size_t nb = ((size_t)b * (3 + BQ_C) + 3) * plane + qs;

    const int c0 = wid * 8;
    #pragma unroll
    for (int k = 0; k < 8; k++) {
        const int c = c0 + k;
        nf[nb + (size_t)c * plane] = __ldg(&fb[(size_t)c * BQ_N + idx]);
    }
}

extern "C" void kernel_launch(void* const* d_in, const int* in_sizes, int n_in,
                              void* d_out, int out_size) {
    const float* key_xyz   = (const float*)d_in[0];
    const float* key_feat  = (const float*)d_in[1];
    const float* query_box = (const float*)d_in[2];
    float* out = (float*)d_out;

    boxquery_group_kernel<<<BQ_B * BQ_NQ, BQ_THREADS>>>(key_xyz, key_feat,
                                                        query_box, out);
}